// round 14
// baseline (speedup 1.0000x reference)
#include <cuda_runtime.h>
#include <cuda_bf16.h>
#include <stdint.h>
#include <math.h>

// Problem constants
#define BB   4
#define TT   2048
#define CC   1024
#define HH   16
#define DD   64
#define BHTD (BB * HH * TT * DD)

// Scratch (device globals: alloc-free per harness rules)
__device__ float g_qkv[3ull * BHTD];            // [3][B,H,T,D] tf32-valued
__device__ float g_att[(size_t)BB * TT * CC];   // [B,T,C] tf32-valued
__device__ float g_xt[(size_t)BB * TT * CC];    // tf32(x)
__device__ float g_wqkv[3 * CC * CC];           // tf32(qkv_w)
__device__ float g_wproj[CC * CC];              // tf32(proj_w)

// ---------------------------------------------------------------------------
// tf32 / mma / ldmatrix / cp.async helpers
// ---------------------------------------------------------------------------
__device__ __forceinline__ uint32_t f2tf(float x) {
    uint32_t u;
    asm("cvt.rna.tf32.f32 %0, %1;" : "=r"(u) : "f"(x));
    return u;
}
__device__ __forceinline__ float f2tff(float x) { return __uint_as_float(f2tf(x)); }

__device__ __forceinline__ float ex2(float x) {
    float r;
    asm("ex2.approx.f32 %0, %1;" : "=f"(r) : "f"(x));
    return r;
}

__device__ __forceinline__ void mma8(float* c,
    uint32_t a0, uint32_t a1, uint32_t a2, uint32_t a3,
    uint32_t b0, uint32_t b1)
{
    asm volatile(
        "mma.sync.aligned.m16n8k8.row.col.f32.tf32.tf32.f32 "
        "{%0,%1,%2,%3},{%4,%5,%6,%7},{%8,%9},{%0,%1,%2,%3};"
        : "+f"(c[0]), "+f"(c[1]), "+f"(c[2]), "+f"(c[3])
        : "r"(a0), "r"(a1), "r"(a2), "r"(a3), "r"(b0), "r"(b1));
}

__device__ __forceinline__ void ldsm4(uint32_t& r0, uint32_t& r1,
                                      uint32_t& r2, uint32_t& r3, uint32_t addr)
{
    asm volatile("ldmatrix.sync.aligned.m8n8.x4.shared.b16 {%0,%1,%2,%3}, [%4];"
                 : "=r"(r0), "=r"(r1), "=r"(r2), "=r"(r3) : "r"(addr));
}

__device__ __forceinline__ void cp16(uint32_t smem, const void* gmem) {
    asm volatile("cp.async.cg.shared.global [%0], [%1], 16;\n"
                 :: "r"(smem), "l"(gmem));
}
__device__ __forceinline__ void cp16ca(uint32_t smem, const void* gmem) {
    asm volatile("cp.async.ca.shared.global [%0], [%1], 16;\n"
                 :: "r"(smem), "l"(gmem));
}
__device__ __forceinline__ void cp_commit() {
    asm volatile("cp.async.commit_group;\n" ::: "memory");
}
template <int N>
__device__ __forceinline__ void cp_wait() {
    asm volatile("cp.async.wait_group %0;\n" :: "n"(N) : "memory");
}

// ---------------------------------------------------------------------------
// Pre-round all three operand buffers to tf32-valued fp32 (one launch)
// ---------------------------------------------------------------------------
#define N4_X  (BB * TT * CC / 4)
#define N4_WQ (3 * CC * CC / 4)
#define N4_WP (CC * CC / 4)

__global__ __launch_bounds__(256) void cvt_all(
    const float4* __restrict__ x, const float4* __restrict__ wq,
    const float4* __restrict__ wp)
{
    float4* ox = (float4*)g_xt;
    float4* oq = (float4*)g_wqkv;
    float4* op = (float4*)g_wproj;
    int total = N4_X + N4_WQ + N4_WP;
    int i = blockIdx.x * blockDim.x + threadIdx.x;
    int stride = gridDim.x * blockDim.x;
    for (; i < total; i += stride) {
        const float4* in; float4* out; int j;
        if (i < N4_X)              { in = x;  out = ox; j = i; }
        else if (i < N4_X + N4_WQ) { in = wq; out = oq; j = i - N4_X; }
        else                       { in = wp; out = op; j = i - N4_X - N4_WQ; }
        float4 v = in[j];
        float4 r;
        r.x = f2tff(v.x); r.y = f2tff(v.y);
        r.z = f2tff(v.z); r.w = f2tff(v.w);
        out[j] = r;
    }
}

// ===========================================================================
// TF32 tensor-core GEMM (unchanged from R13): CTA 128x256x64, 8 warps 64x64,
// LDSM loads, 2-stage 192KB ring.
// ===========================================================================
#define GBM 128
#define GBN 256
#define GBK 64
#define A_FLOATS (GBM * GBK)
#define B_FLOATS (GBN * GBK)
#define STAGE_FLOATS (A_FLOATS + B_FLOATS)
#define NSTAGE 2
#define SMEM_GEMM (NSTAGE * STAGE_FLOATS * 4)

__global__ __launch_bounds__(256, 1) void gemm_tc(
    const float* __restrict__ Bt,
    const float* __restrict__ bias, float* __restrict__ Cout,
    int M, int N, int K, int mode)
{
    extern __shared__ float smem[];
    const float* A = (mode == 2) ? g_att : g_xt;

    int tid = threadIdx.x, lane = tid & 31, w = tid >> 5;
    int wm0 = (w >> 2) * 64;
    int wn0 = (w & 3) * 64;
    int m0 = blockIdx.y * GBM, n0 = blockIdx.x * GBN;

    uint32_t smem_base = (uint32_t)__cvta_generic_to_shared(smem);

    float acc[4][8][4];
#pragma unroll
    for (int mt = 0; mt < 4; mt++)
#pragma unroll
        for (int nt = 0; nt < 8; nt++)
#pragma unroll
            for (int j = 0; j < 4; j++) acc[mt][nt][j] = 0.f;

    int keyx = lane & 7;
    int ha = lane >> 4;
    int hb = (lane >> 3) & 1;
    uint32_t aab[4], bab[4];
#pragma unroll
    for (int mt = 0; mt < 4; mt++)
        aab[mt] = (uint32_t)(wm0 + mt * 16 + (lane & 15)) * 256u;
#pragma unroll
    for (int p = 0; p < 4; p++)
        bab[p] = (uint32_t)(wn0 + p * 16 + (lane & 7) + ((lane >> 4) << 3)) * 256u;

    int nK = K / GBK;

    auto stage_tile = [&](int st, int kk) {
        uint32_t sA = smem_base + (uint32_t)st * (STAGE_FLOATS * 4);
        uint32_t sB = sA + A_FLOATS * 4;
#pragma unroll
        for (int i = 0; i < 8; i++) {
            int l = tid + i * 256;
            int row = l >> 4, q = l & 15;
            uint32_t soff = (uint32_t)row * 256u + (uint32_t)((q ^ (row & 7)) << 4);
            cp16(sA + soff, A + (size_t)(m0 + row) * K + kk + q * 4);
        }
#pragma unroll
        for (int i = 0; i < 16; i++) {
            int l = tid + i * 256;
            int row = l >> 4, q = l & 15;
            uint32_t soff = (uint32_t)row * 256u + (uint32_t)((q ^ (row & 7)) << 4);
            cp16(sB + soff, Bt + (size_t)(n0 + row) * K + kk + q * 4);
        }
        cp_commit();
    };

    stage_tile(0, 0);

    for (int kt = 0; kt < nK; kt++) {
        cp_wait<0>();
        __syncthreads();

        if (kt + 1 < nK) stage_tile((kt + 1) & 1, (kt + 1) * GBK);

        uint32_t As_b = smem_base + (uint32_t)(kt & 1) * (STAGE_FLOATS * 4);
        uint32_t Bs_b = As_b + A_FLOATS * 4;

#pragma unroll
        for (int kc = 0; kc < 8; kc++) {
            uint32_t ca = (uint32_t)(((2 * kc + ha) ^ keyx) << 4);
            uint32_t cb = (uint32_t)(((2 * kc + hb) ^ keyx) << 4);
            uint32_t a[4][4];
#pragma unroll
            for (int mt = 0; mt < 4; mt++)
                ldsm4(a[mt][0], a[mt][1], a[mt][2], a[mt][3], As_b + aab[mt] + ca);
#pragma unroll
            for (int p = 0; p < 4; p++) {
                uint32_t bv0, bv1, bv2, bv3;
                ldsm4(bv0, bv1, bv2, bv3, Bs_b + bab[p] + cb);
#pragma unroll
                for (int mt = 0; mt < 4; mt++) {
                    mma8(acc[mt][2 * p],     a[mt][0], a[mt][1], a[mt][2], a[mt][3], bv0, bv1);
                    mma8(acc[mt][2 * p + 1], a[mt][0], a[mt][1], a[mt][2], a[mt][3], bv2, bv3);
                }
            }
        }
    }

#pragma unroll
    for (int mt = 0; mt < 4; mt++) {
#pragma unroll
        for (int h = 0; h < 2; h++) {
            int m = m0 + wm0 + mt * 16 + (lane >> 2) + h * 8;
#pragma unroll
            for (int nt = 0; nt < 8; nt++) {
                int n = n0 + wn0 + nt * 8 + 2 * (lane & 3);
                float2 r;
                r.x = acc[mt][nt][h * 2 + 0] + bias[n];
                r.y = acc[mt][nt][h * 2 + 1] + bias[n + 1];
                if (mode == 1) {
                    r.x = f2tff(r.x);
                    r.y = f2tff(r.y);
                    int which = n >> 10;
                    int hh = (n >> 6) & (HH - 1);
                    int d = n & (DD - 1);
                    int b = m >> 11;
                    int t = m & (TT - 1);
                    float* p = g_qkv + (size_t)which * BHTD
                             + ((((size_t)b * HH + hh) * TT + t) * DD + d);
                    *(float2*)p = r;
                } else {
                    *(float2*)(Cout + (size_t)m * N + n) = r;
                }
            }
        }
    }
}

// ===========================================================================
// Flash attention v5 (causal): 128-key staged tiles, computed as two 64-col
// halves inside ONE barrier round. Q-block 256, 8 warps x 32 rows, 1 CTA/SM.
// ===========================================================================
#define ATPB 256
#define KT   128
#define KSD 68
#define VSD 72
#define KVSTG (KT * KSD + KT * VSD)           // 17920 floats per stage
#define PSM_FLOATS (8 * 32 * KSD)             // 17408
#define SMEM_ATTN ((2 * KVSTG + PSM_FLOATS) * 4)   // 212,992 B
#define QSCALE (0.125f * 1.44269504088896f)

__global__ __launch_bounds__(ATPB, 1) void attn_tc()
{
    extern __shared__ float sm[];
    float* Psm = sm + 2 * KVSTG;

    int qb = gridDim.x - 1 - blockIdx.x;     // big blocks first
    int bh = blockIdx.y;
    int q0 = qb * 256;
    int tid = threadIdx.x, lane = tid & 31, w = tid >> 5;
    int qw0 = q0 + w * 32;

    const float* qp = g_qkv + (size_t)bh * TT * DD;
    const float* kp = qp + (size_t)BHTD;
    const float* vp = qp + 2ull * BHTD;

    uint32_t smem_base = (uint32_t)__cvta_generic_to_shared(sm);

    // staging: KT rows x 16 chunks for each of K and V; 8 chunks/thread each
    int srow[8], sdq[8];
#pragma unroll
    for (int it = 0; it < 8; it++) {
        int l = tid + it * ATPB;     // 0..2047
        srow[it] = l >> 4;           // 0..127
        sdq[it]  = (l & 15) * 4;
    }

    auto stage_kv = [&](int st, int krow0) {
        uint32_t kb = smem_base + (uint32_t)st * (KVSTG * 4);
        uint32_t vb = kb + KT * KSD * 4;
#pragma unroll
        for (int it = 0; it < 8; it++) {
            int row = srow[it], dq = sdq[it];
            cp16ca(kb + (row * KSD + dq) * 4, kp + (size_t)(krow0 + row) * DD + dq);
            cp16ca(vb + (row * VSD + dq) * 4, vp + (size_t)(krow0 + row) * DD + dq);
        }
        cp_commit();
    };

    // prologue: stage tile 0 (keys 0..127)
    stage_kv(0, 0);

    // ldmatrix row bases for K fragments within a 64-row half
    uint32_t krow[4];
#pragma unroll
    for (int p = 0; p < 4; p++) {
        int row = p * 16 + (lane & 7) + ((lane >> 4) << 3);
        krow[p] = (uint32_t)(row * KSD) * 4u + (uint32_t)(((lane >> 3) & 1) << 4);
    }

    // Q -> registers, two 16-row groups, exp2-domain scale folded
    uint32_t qa[2][8][4];
#pragma unroll
    for (int g = 0; g < 2; g++) {
        int r = qw0 + g * 16 + (lane >> 2);
#pragma unroll
        for (int c = 0; c < 8; c++) {
            int col = c * 8 + (lane & 3);
            qa[g][c][0] = f2tf(qp[(size_t)r * DD + col] * QSCALE);
            qa[g][c][1] = f2tf(qp[(size_t)(r + 8) * DD + col] * QSCALE);
            qa[g][c][2] = f2tf(qp[(size_t)r * DD + col + 4] * QSCALE);
            qa[g][c][3] = f2tf(qp[(size_t)(r + 8) * DD + col + 4] * QSCALE);
        }
    }

    float m_i[2][2], l_i[2][2];
    float oacc[2][8][4];
#pragma unroll
    for (int g = 0; g < 2; g++) {
        m_i[g][0] = m_i[g][1] = -1e30f;
        l_i[g][0] = l_i[g][1] = 0.f;
#pragma unroll
        for (int nt = 0; nt < 8; nt++)
#pragma unroll
            for (int j = 0; j < 4; j++) oacc[g][nt][j] = 0.f;
    }

    int jbmax = 2 * qb + 1;          // 128-key tiles
    for (int jb = 0; jb <= jbmax; jb++) {
        int k0t = jb * KT;
        cp_wait<0>();
        __syncthreads();             // tile jb visible; all done with other stage

        if (jb < jbmax) stage_kv((jb + 1) & 1, k0t + KT);

        uint32_t Kb0 = smem_base + (uint32_t)((jb & 1) * (KVSTG * 4));
        const uint32_t* Vu0 = (const uint32_t*)(sm + (size_t)(jb & 1) * KVSTG + KT * KSD);

        // two 64-column halves inside one barrier round
#pragma unroll
        for (int h2 = 0; h2 < 2; h2++) {
            int k0 = k0t + h2 * 64;
            if (k0 > qw0 + 31) break;
            uint32_t Kb = Kb0 + (uint32_t)(h2 * 64 * KSD * 4);
            const uint32_t* Vu = Vu0 + (size_t)h2 * 64 * VSD;

            float sacc[2][8][4];
#pragma unroll
            for (int g = 0; g < 2; g++)
#pragma unroll
                for (int nt = 0; nt < 8; nt++)
#pragma unroll
                    for (int j = 0; j < 4; j++) sacc[g][nt][j] = 0.f;
#pragma unroll
            for (int kc = 0; kc < 8; kc++) {
#pragma unroll
                for (int p = 0; p < 4; p++) {
                    uint32_t b0, b1, b2, b3;
                    ldsm4(b0, b1, b2, b3, Kb + krow[p] + (uint32_t)(kc * 32));
                    mma8(sacc[0][2 * p],     qa[0][kc][0], qa[0][kc][1], qa[0][kc][2], qa[0][kc][3], b0, b1);
                    mma8(sacc[1][2 * p],     qa[1][kc][0], qa[1][kc][1], qa[1][kc][2], qa[1][kc][3], b0, b1);
                    mma8(sacc[0][2 * p + 1], qa[0][kc][0], qa[0][kc][1], qa[0][kc][2], qa[0][kc][3], b2, b3);
                    mma8(sacc[1][2 * p + 1], qa[1][kc][0], qa[1][kc][1], qa[1][kc][2], qa[1][kc][3], b2, b3);
                }
            }

            if (k0 + 63 > qw0) {
#pragma unroll
                for (int g = 0; g < 2; g++) {
                    int r0 = qw0 + g * 16 + (lane >> 2);
#pragma unroll
                    for (int nt = 0; nt < 8; nt++) {
                        int col = k0 + nt * 8 + 2 * (lane & 3);
                        if (col     > r0)     sacc[g][nt][0] = -1e30f;
                        if (col + 1 > r0)     sacc[g][nt][1] = -1e30f;
                        if (col     > r0 + 8) sacc[g][nt][2] = -1e30f;
                        if (col + 1 > r0 + 8) sacc[g][nt][3] = -1e30f;
                    }
                }
            }

#pragma unroll
            for (int g = 0; g < 2; g++) {
#pragma unroll
                for (int h = 0; h < 2; h++) {
                    float mx = -1e30f;
#pragma unroll
                    for (int nt = 0; nt < 8; nt++) {
                        mx = fmaxf(mx, sacc[g][nt][h * 2 + 0]);
                        mx = fmaxf(mx, sacc[g][nt][h * 2 + 1]);
                    }
                    mx = fmaxf(mx, __shfl_xor_sync(0xffffffffu, mx, 1));
                    mx = fmaxf(mx, __shfl_xor_sync(0xffffffffu, mx, 2));
                    float mnew = fmaxf(m_i[g][h], mx);
                    float alpha = ex2(m_i[g][h] - mnew);
                    float rs = 0.f;
#pragma unroll
                    for (int nt = 0; nt < 8; nt++) {
                        float p0 = ex2(sacc[g][nt][h * 2 + 0] - mnew);
                        float p1 = ex2(sacc[g][nt][h * 2 + 1] - mnew);
                        sacc[g][nt][h * 2 + 0] = p0;
                        sacc[g][nt][h * 2 + 1] = p1;
                        rs += p0 + p1;
                    }
                    rs += __shfl_xor_sync(0xffffffffu, rs, 1);
                    rs += __shfl_xor_sync(0xffffffffu, rs, 2);
                    l_i[g][h] = l_i[g][h] * alpha + rs;
                    m_i[g][h] = mnew;
#pragma unroll
                    for (int nt = 0; nt < 8; nt++) {
                        oacc[g][nt][h * 2 + 0] *= alpha;
                        oacc[g][nt][h * 2 + 1] *= alpha;
                    }
                }
            }

            // P -> per-warp smem RAW fp32 (HW truncates to tf32 in MMA)
            float* Pw = Psm + w * 32 * KSD;
#pragma unroll
            for (int g = 0; g < 2; g++) {
#pragma unroll
                for (int nt = 0; nt < 8; nt++) {
                    int col = nt * 8 + 2 * (lane & 3);
                    float2 p0, p1;
                    p0.x = sacc[g][nt][0]; p0.y = sacc[g][nt][1];
                    p1.x = sacc[g][nt][2]; p1.y = sacc[g][nt][3];
                    *(float2*)&Pw[(g * 16 + (lane >> 2)) * KSD + col] = p0;
                    *(float2*)&Pw[(g * 16 + (lane >> 2) + 8) * KSD + col] = p1;
                }
            }
            __syncwarp();
            const uint32_t* Pwu = (const uint32_t*)Pw;
#pragma unroll
            for (int kc = 0; kc < 8; kc++) {
                uint32_t a[2][4];
#pragma unroll
                for (int g = 0; g < 2; g++) {
                    a[g][0] = Pwu[(g * 16 + (lane >> 2)) * KSD + kc * 8 + (lane & 3)];
                    a[g][1] = Pwu[(g * 16 + (lane >> 2) + 8) * KSD + kc * 8 + (lane & 3)];
                    a[g][2] = Pwu[(g * 16 + (lane >> 2)) * KSD + kc * 8 + 4 + (lane & 3)];
                    a[g][3] = Pwu[(g * 16 + (lane >> 2) + 8) * KSD + kc * 8 + 4 + (lane & 3)];
                }
#pragma unroll
                for (int nt = 0; nt < 8; nt++) {
                    uint32_t b0 = Vu[(kc * 8 + (lane & 3)) * VSD + nt * 8 + (lane >> 2)];
                    uint32_t b1 = Vu[(kc * 8 + 4 + (lane & 3)) * VSD + nt * 8 + (lane >> 2)];
                    mma8(oacc[0][nt], a[0][0], a[0][1], a[0][2], a[0][3], b0, b1);
                    mma8(oacc[1][nt], a[1][0], a[1][1], a[1][2], a[1][3], b0, b1);
                }
            }
            __syncwarp();   // Pw reuse safety between halves (per-warp buffer)
        }
    }

    // normalize + store to g_att [B,T,C] (tf32-rounded for proj)
    int bb = bh >> 4, hh = bh & (HH - 1);
#pragma unroll
    for (int g = 0; g < 2; g++) {
#pragma unroll
        for (int h = 0; h < 2; h++) {
            int row = qw0 + g * 16 + (lane >> 2) + h * 8;
            float inv = 1.f / l_i[g][h];
#pragma unroll
            for (int nt = 0; nt < 8; nt++) {
                int col = hh * DD + nt * 8 + 2 * (lane & 3);
                float2 r;
                r.x = f2tff(oacc[g][nt][h * 2 + 0] * inv);
                r.y = f2tff(oacc[g][nt][h * 2 + 1] * inv);
                *(float2*)(g_att + ((size_t)bb * TT + row) * CC + col) = r;
            }
        }
    }
}

// ===========================================================================
// Launch
// ===========================================================================
extern "C" void kernel_launch(void* const* d_in, const int* in_sizes, int n_in,
                              void* d_out, int out_size)
{
    (void)in_sizes; (void)n_in; (void)out_size;
    const float* x      = (const float*)d_in[0];
    const float* qkv_w  = (const float*)d_in[1];
    const float* qkv_b  = (const float*)d_in[2];
    const float* proj_w = (const float*)d_in[3];
    const float* proj_b = (const float*)d_in[4];
    float* out = (float*)d_out;

    cudaFuncSetAttribute(gemm_tc,
                         cudaFuncAttributeMaxDynamicSharedMemorySize, SMEM_GEMM);
    cudaFuncSetAttribute(attn_tc,
                         cudaFuncAttributeMaxDynamicSharedMemorySize, SMEM_ATTN);

    // Device addresses of __device__ symbols (query, not allocation).
    float* wq; float* wp;
    cudaGetSymbolAddress((void**)&wq, g_wqkv);
    cudaGetSymbolAddress((void**)&wp, g_wproj);

    // 0) pre-round all operands to tf32 grid (single launch)
    cvt_all<<<2048, 256>>>((const float4*)x, (const float4*)qkv_w,
                           (const float4*)proj_w);

    // 1) QKV projection + bias -> scatter tf32 [3][B,H,T,D]
    gemm_tc<<<dim3(3 * CC / GBN, BB * TT / GBM), 256, SMEM_GEMM>>>(
        wq, qkv_b, nullptr, BB * TT, 3 * CC, CC, 1);

    // 2) Causal flash attention -> g_att [B,T,C]
    attn_tc<<<dim3(TT / 256, BB * HH), ATPB, SMEM_ATTN>>>();

    // 3) Output projection + bias -> d_out
    gemm_tc<<<dim3(CC / GBN, BB * TT / GBM), 256, SMEM_GEMM>>>(
        wp, proj_b, out, BB * TT, CC, CC, 2);
}

// round 15
// speedup vs baseline: 1.7869x; 1.7869x over previous
#include <cuda_runtime.h>
#include <cuda_fp16.h>
#include <stdint.h>

// Problem constants
#define BB   4
#define TT   2048
#define CC   1024
#define HH   16
#define DD   64
#define BHTD (BB * HH * TT * DD)

// Scratch (device globals)
__device__ __half g_qkvh[3ull * BHTD];           // [3][B,H,T,D] fp16
__device__ __half g_atth[(size_t)BB * TT * CC];  // [B,T,C] fp16
__device__ __half g_xh[(size_t)BB * TT * CC];    // fp16(x)
__device__ __half g_wqh[3 * CC * CC];            // fp16(qkv_w)
__device__ __half g_wph[CC * CC];                // fp16(proj_w)

// ---------------------------------------------------------------------------
// helpers
// ---------------------------------------------------------------------------
__device__ __forceinline__ float ex2(float x) {
    float r;
    asm("ex2.approx.f32 %0, %1;" : "=f"(r) : "f"(x));
    return r;
}

__device__ __forceinline__ void mma16(float* c,
    uint32_t a0, uint32_t a1, uint32_t a2, uint32_t a3,
    uint32_t b0, uint32_t b1)
{
    asm volatile(
        "mma.sync.aligned.m16n8k16.row.col.f32.f16.f16.f32 "
        "{%0,%1,%2,%3},{%4,%5,%6,%7},{%8,%9},{%0,%1,%2,%3};"
        : "+f"(c[0]), "+f"(c[1]), "+f"(c[2]), "+f"(c[3])
        : "r"(a0), "r"(a1), "r"(a2), "r"(a3), "r"(b0), "r"(b1));
}

__device__ __forceinline__ void ldsm4(uint32_t& r0, uint32_t& r1,
                                      uint32_t& r2, uint32_t& r3, uint32_t addr)
{
    asm volatile("ldmatrix.sync.aligned.m8n8.x4.shared.b16 {%0,%1,%2,%3}, [%4];"
                 : "=r"(r0), "=r"(r1), "=r"(r2), "=r"(r3) : "r"(addr));
}
__device__ __forceinline__ void ldsm4t(uint32_t& r0, uint32_t& r1,
                                       uint32_t& r2, uint32_t& r3, uint32_t addr)
{
    asm volatile("ldmatrix.sync.aligned.m8n8.x4.trans.shared.b16 {%0,%1,%2,%3}, [%4];"
                 : "=r"(r0), "=r"(r1), "=r"(r2), "=r"(r3) : "r"(addr));
}

__device__ __forceinline__ void cp16(uint32_t smem, const void* gmem) {
    asm volatile("cp.async.cg.shared.global [%0], [%1], 16;\n"
                 :: "r"(smem), "l"(gmem));
}
__device__ __forceinline__ void cp16ca(uint32_t smem, const void* gmem) {
    asm volatile("cp.async.ca.shared.global [%0], [%1], 16;\n"
                 :: "r"(smem), "l"(gmem));
}
__device__ __forceinline__ void cp_commit() {
    asm volatile("cp.async.commit_group;\n" ::: "memory");
}
template <int N>
__device__ __forceinline__ void cp_wait() {
    asm volatile("cp.async.wait_group %0;\n" :: "n"(N) : "memory");
}

// ---------------------------------------------------------------------------
// Convert all fp32 operands to fp16 (one launch). float4 -> 2x half2.
// ---------------------------------------------------------------------------
#define N4_X  (BB * TT * CC / 4)
#define N4_WQ (3 * CC * CC / 4)
#define N4_WP (CC * CC / 4)

__global__ __launch_bounds__(256) void cvt_all(
    const float4* __restrict__ x, const float4* __restrict__ wq,
    const float4* __restrict__ wp)
{
    int total = N4_X + N4_WQ + N4_WP;
    int i = blockIdx.x * blockDim.x + threadIdx.x;
    int stride = gridDim.x * blockDim.x;
    for (; i < total; i += stride) {
        const float4* in; __half* out; int j;
        if (i < N4_X)              { in = x;  out = g_xh;  j = i; }
        else if (i < N4_X + N4_WQ) { in = wq; out = g_wqh; j = i - N4_X; }
        else                       { in = wp; out = g_wph; j = i - N4_X - N4_WQ; }
        float4 v = in[j];
        __half2 h0 = __floats2half2_rn(v.x, v.y);
        __half2 h1 = __floats2half2_rn(v.z, v.w);
        *(uint2*)(out + (size_t)j * 4) =
            make_uint2(*(uint32_t*)&h0, *(uint32_t*)&h1);
    }
}

// ===========================================================================
// FP16 tensor-core GEMM: C[m,n] = sum_k A[m,k]*Bt[n,k] + bias[n]
// CTA 128x256x64, 8 warps 64x64, m16n8k16 HMMA, LDSM fragment loads.
// 3-stage cp.async ring (48KB/stage). Rows = 64 halves = 128B, XOR swizzle.
// mode 1: scatter fp16 into g_qkvh; else: fp32 store + bias.
// ===========================================================================
#define GBM 128
#define GBN 256
#define GBK 64
#define A_HALVES (GBM * GBK)                    // 8192 (16KB)
#define B_HALVES (GBN * GBK)                    // 32768... (32KB)
#define STAGE_BYTES ((A_HALVES + B_HALVES) * 2) // 49152
#define NSTAGE 3
#define SMEM_GEMM (NSTAGE * STAGE_BYTES)        // 147456

__global__ __launch_bounds__(256, 1) void gemm_h(
    const __half* __restrict__ A, const __half* __restrict__ Bt,
    const float* __restrict__ bias, float* __restrict__ Cout,
    int M, int N, int K, int mode)
{
    extern __shared__ char smc[];
    int tid = threadIdx.x, lane = tid & 31, w = tid >> 5;
    int wm0 = (w >> 2) * 64;
    int wn0 = (w & 3) * 64;
    int m0 = blockIdx.y * GBM, n0 = blockIdx.x * GBN;

    uint32_t smem_base = (uint32_t)__cvta_generic_to_shared(smc);

    float acc[4][8][4];
#pragma unroll
    for (int mt = 0; mt < 4; mt++)
#pragma unroll
        for (int nt = 0; nt < 8; nt++)
#pragma unroll
            for (int j = 0; j < 4; j++) acc[mt][nt][j] = 0.f;

    int keyx = lane & 7;
    uint32_t ha = lane >> 4;            // A chunk half
    uint32_t hb = (lane >> 3) & 1;      // B chunk half
    uint32_t aab[4], bab[4];
#pragma unroll
    for (int mt = 0; mt < 4; mt++)
        aab[mt] = (uint32_t)(wm0 + mt * 16 + (lane & 15)) * 128u;
#pragma unroll
    for (int p = 0; p < 4; p++)
        bab[p] = (uint32_t)(wn0 + p * 16 + (lane & 7) + ((lane >> 4) << 3)) * 128u;

    int nK = K / GBK;

    // staging: A 4 chunks/thread, B 8 chunks/thread (chunk = 16B = 8 halves)
    auto stage_tile = [&](int st, int kk) {
        uint32_t sA = smem_base + (uint32_t)st * STAGE_BYTES;
        uint32_t sB = sA + A_HALVES * 2;
#pragma unroll
        for (int i = 0; i < 4; i++) {
            int l = tid + i * 256;
            int row = l >> 3, q = l & 7;
            uint32_t soff = (uint32_t)row * 128u + (uint32_t)((q ^ (row & 7)) << 4);
            cp16(sA + soff, A + (size_t)(m0 + row) * K + kk + q * 8);
        }
#pragma unroll
        for (int i = 0; i < 8; i++) {
            int l = tid + i * 256;
            int row = l >> 3, q = l & 7;
            uint32_t soff = (uint32_t)row * 128u + (uint32_t)((q ^ (row & 7)) << 4);
            cp16(sB + soff, Bt + (size_t)(n0 + row) * K + kk + q * 8);
        }
        cp_commit();
    };

    stage_tile(0, 0);
    stage_tile(1, GBK);

    int rd_stage = 0, wr_stage = 2;
    for (int kt = 0; kt < nK; kt++) {
        if (kt + 1 < nK) cp_wait<1>(); else cp_wait<0>();
        __syncthreads();

        if (kt + 2 < nK) stage_tile(wr_stage, (kt + 2) * GBK);
        if (++wr_stage == NSTAGE) wr_stage = 0;

        uint32_t As_b = smem_base + (uint32_t)rd_stage * STAGE_BYTES;
        uint32_t Bs_b = As_b + A_HALVES * 2;
        if (++rd_stage == NSTAGE) rd_stage = 0;

#pragma unroll
        for (int kc = 0; kc < 4; kc++) {
            uint32_t ca = (uint32_t)(((2 * kc + ha) ^ keyx) << 4);
            uint32_t cb = (uint32_t)(((2 * kc + hb) ^ keyx) << 4);
            uint32_t a[4][4];
#pragma unroll
            for (int mt = 0; mt < 4; mt++)
                ldsm4(a[mt][0], a[mt][1], a[mt][2], a[mt][3], As_b + aab[mt] + ca);
#pragma unroll
            for (int p = 0; p < 4; p++) {
                uint32_t bv0, bv1, bv2, bv3;
                ldsm4(bv0, bv1, bv2, bv3, Bs_b + bab[p] + cb);
#pragma unroll
                for (int mt = 0; mt < 4; mt++) {
                    mma16(acc[mt][2 * p],     a[mt][0], a[mt][1], a[mt][2], a[mt][3], bv0, bv1);
                    mma16(acc[mt][2 * p + 1], a[mt][0], a[mt][1], a[mt][2], a[mt][3], bv2, bv3);
                }
            }
        }
    }

    // Epilogue
#pragma unroll
    for (int mt = 0; mt < 4; mt++) {
#pragma unroll
        for (int h = 0; h < 2; h++) {
            int m = m0 + wm0 + mt * 16 + (lane >> 2) + h * 8;
#pragma unroll
            for (int nt = 0; nt < 8; nt++) {
                int n = n0 + wn0 + nt * 8 + 2 * (lane & 3);
                float rx = acc[mt][nt][h * 2 + 0] + bias[n];
                float ry = acc[mt][nt][h * 2 + 1] + bias[n + 1];
                if (mode == 1) {
                    int which = n >> 10;
                    int hh = (n >> 6) & (HH - 1);
                    int d = n & (DD - 1);
                    int b = m >> 11;
                    int t = m & (TT - 1);
                    __half* p = g_qkvh + (size_t)which * BHTD
                              + ((((size_t)b * HH + hh) * TT + t) * DD + d);
                    *(__half2*)p = __floats2half2_rn(rx, ry);
                } else {
                    float2 r; r.x = rx; r.y = ry;
                    *(float2*)(Cout + (size_t)m * N + n) = r;
                }
            }
        }
    }
}

// ===========================================================================
// FP16 flash attention (causal). Q-block 256, 8 warps x 32 rows.
// K frags: ldmatrix; V frags: ldmatrix.trans (no scalar LDS); P staged half2.
// cp.async double-buffered 64-key tiles. Softmax exp2 domain.
// ===========================================================================
#define ATPB 256
#define ROWB 128                         // 64 halves per row
#define KVTILE (64 * ROWB)               // 8KB
#define KVSTG  (2 * KVTILE)              // K+V = 16KB per stage
#define PSMB   (8 * 32 * ROWB)           // 32KB (per-warp P)
#define SMEM_ATTN (2 * KVSTG + PSMB)     // 64KB
#define QSCALE (0.125f * 1.44269504088896f)

__global__ __launch_bounds__(ATPB, 1) void attn_h()
{
    extern __shared__ char smc[];
    uint32_t smem_base = (uint32_t)__cvta_generic_to_shared(smc);
    uint32_t psm_base = smem_base + 2 * KVSTG;

    int qb = gridDim.x - 1 - blockIdx.x;
    int bh = blockIdx.y;
    int q0 = qb * 256;
    int tid = threadIdx.x, lane = tid & 31, w = tid >> 5;
    int qw0 = q0 + w * 32;

    const __half* qp = g_qkvh + (size_t)bh * TT * DD;
    const __half* kp = qp + (size_t)BHTD;
    const __half* vp = qp + 2ull * BHTD;

    auto stage_kv = [&](int st, int k0) {
        uint32_t kb = smem_base + (uint32_t)st * KVSTG;
        uint32_t vb = kb + KVTILE;
#pragma unroll
        for (int it = 0; it < 2; it++) {
            int l = tid + it * ATPB;     // 0..511
            int row = l >> 3, q = l & 7;
            uint32_t soff = (uint32_t)row * 128u + (uint32_t)((q ^ (row & 7)) << 4);
            cp16ca(kb + soff, kp + (size_t)(k0 + row) * DD + q * 8);
            cp16ca(vb + soff, vp + (size_t)(k0 + row) * DD + q * 8);
        }
        cp_commit();
    };

    stage_kv(0, 0);

    // fragment address bases
    int keyx = lane & 7;
    uint32_t krow[4];                                 // K B-frags (ldsm)
#pragma unroll
    for (int p = 0; p < 4; p++)
        krow[p] = (uint32_t)(p * 16 + (lane & 7) + ((lane >> 4) << 3)) * 128u;
    uint32_t vrow = (uint32_t)((lane & 7) + (((lane >> 3) & 1) << 3)) * 128u;  // V (trans)
    uint32_t hb = (lane >> 3) & 1;
    uint32_t ha = lane >> 4;

    // Q -> registers as fp16 A-frags, scale folded (rn to half after scale)
    uint32_t qa[2][4][4];
#pragma unroll
    for (int g = 0; g < 2; g++) {
        int r = qw0 + g * 16 + (lane >> 2);
#pragma unroll
        for (int kc = 0; kc < 4; kc++) {
            int kb = kc * 16 + 2 * (lane & 3);
#pragma unroll
            for (int s = 0; s < 4; s++) {
                int rr = r + ((s & 1) ? 8 : 0);
                int cc = kb + ((s & 2) ? 8 : 0);
                float f0 = __half2float(qp[(size_t)rr * DD + cc])     * QSCALE;
                float f1 = __half2float(qp[(size_t)rr * DD + cc + 1]) * QSCALE;
                __half2 hq = __floats2half2_rn(f0, f1);
                qa[g][kc][s] = *(uint32_t*)&hq;
            }
        }
    }

    float m_i[2][2], l_i[2][2];
    float oacc[2][8][4];
#pragma unroll
    for (int g = 0; g < 2; g++) {
        m_i[g][0] = m_i[g][1] = -1e30f;
        l_i[g][0] = l_i[g][1] = 0.f;
#pragma unroll
        for (int nt = 0; nt < 8; nt++)
#pragma unroll
            for (int j = 0; j < 4; j++) oacc[g][nt][j] = 0.f;
    }

    int jbmax = 4 * qb + 3;
    for (int jb = 0; jb <= jbmax; jb++) {
        int k0 = jb * 64;
        cp_wait<0>();
        __syncthreads();

        if (jb < jbmax) stage_kv((jb + 1) & 1, k0 + 64);

        uint32_t Kb = smem_base + (uint32_t)((jb & 1) * KVSTG);
        uint32_t Vb = Kb + KVTILE;

        if (k0 <= qw0 + 31) {
            // S = Q K^T
            float sacc[2][8][4];
#pragma unroll
            for (int g = 0; g < 2; g++)
#pragma unroll
                for (int nt = 0; nt < 8; nt++)
#pragma unroll
                    for (int j = 0; j < 4; j++) sacc[g][nt][j] = 0.f;
#pragma unroll
            for (int kc = 0; kc < 4; kc++) {
                uint32_t cb = (uint32_t)(((2 * kc + hb) ^ keyx) << 4);
#pragma unroll
                for (int p = 0; p < 4; p++) {
                    uint32_t b0, b1, b2, b3;
                    ldsm4(b0, b1, b2, b3, Kb + krow[p] + cb);
                    mma16(sacc[0][2 * p],     qa[0][kc][0], qa[0][kc][1], qa[0][kc][2], qa[0][kc][3], b0, b1);
                    mma16(sacc[1][2 * p],     qa[1][kc][0], qa[1][kc][1], qa[1][kc][2], qa[1][kc][3], b0, b1);
                    mma16(sacc[0][2 * p + 1], qa[0][kc][0], qa[0][kc][1], qa[0][kc][2], qa[0][kc][3], b2, b3);
                    mma16(sacc[1][2 * p + 1], qa[1][kc][0], qa[1][kc][1], qa[1][kc][2], qa[1][kc][3], b2, b3);
                }
            }

            if (k0 + 63 > qw0) {
#pragma unroll
                for (int g = 0; g < 2; g++) {
                    int r0 = qw0 + g * 16 + (lane >> 2);
#pragma unroll
                    for (int nt = 0; nt < 8; nt++) {
                        int col = k0 + nt * 8 + 2 * (lane & 3);
                        if (col     > r0)     sacc[g][nt][0] = -1e30f;
                        if (col + 1 > r0)     sacc[g][nt][1] = -1e30f;
                        if (col     > r0 + 8) sacc[g][nt][2] = -1e30f;
                        if (col + 1 > r0 + 8) sacc[g][nt][3] = -1e30f;
                    }
                }
            }

            // online softmax (exp2 domain)
#pragma unroll
            for (int g = 0; g < 2; g++) {
#pragma unroll
                for (int h = 0; h < 2; h++) {
                    float mx = -1e30f;
#pragma unroll
                    for (int nt = 0; nt < 8; nt++) {
                        mx = fmaxf(mx, sacc[g][nt][h * 2 + 0]);
                        mx = fmaxf(mx, sacc[g][nt][h * 2 + 1]);
                    }
                    mx = fmaxf(mx, __shfl_xor_sync(0xffffffffu, mx, 1));
                    mx = fmaxf(mx, __shfl_xor_sync(0xffffffffu, mx, 2));
                    float mnew = fmaxf(m_i[g][h], mx);
                    float alpha = ex2(m_i[g][h] - mnew);
                    float rs = 0.f;
#pragma unroll
                    for (int nt = 0; nt < 8; nt++) {
                        float p0 = ex2(sacc[g][nt][h * 2 + 0] - mnew);
                        float p1 = ex2(sacc[g][nt][h * 2 + 1] - mnew);
                        sacc[g][nt][h * 2 + 0] = p0;
                        sacc[g][nt][h * 2 + 1] = p1;
                        rs += p0 + p1;
                    }
                    rs += __shfl_xor_sync(0xffffffffu, rs, 1);
                    rs += __shfl_xor_sync(0xffffffffu, rs, 2);
                    l_i[g][h] = l_i[g][h] * alpha + rs;
                    m_i[g][h] = mnew;
#pragma unroll
                    for (int nt = 0; nt < 8; nt++) {
                        oacc[g][nt][h * 2 + 0] *= alpha;
                        oacc[g][nt][h * 2 + 1] *= alpha;
                    }
                }
            }

            // P -> per-warp smem as fp16 (rn)
            uint32_t Pw = psm_base + (uint32_t)w * 32 * ROWB;
#pragma unroll
            for (int g = 0; g < 2; g++) {
                int r0 = g * 16 + (lane >> 2);
#pragma unroll
                for (int nt = 0; nt < 8; nt++) {
                    uint32_t coff = (uint32_t)(((nt ^ (r0 & 7)) << 4) + 4 * (lane & 3));
                    __half2 p0 = __floats2half2_rn(sacc[g][nt][0], sacc[g][nt][1]);
                    __half2 p1 = __floats2half2_rn(sacc[g][nt][2], sacc[g][nt][3]);
                    *(__half2*)(smc + (Pw - smem_base) + (uint32_t)r0 * 128u + coff) = p0;
                    *(__half2*)(smc + (Pw - smem_base) + (uint32_t)(r0 + 8) * 128u + coff) = p1;
                }
            }
            __syncwarp();

            // O += P V   (A: ldsm on P; B: ldsm.trans on V)
#pragma unroll
            for (int kc = 0; kc < 4; kc++) {
                uint32_t ca = (uint32_t)(((2 * kc + ha) ^ keyx) << 4);
                uint32_t a[2][4];
#pragma unroll
                for (int g = 0; g < 2; g++)
                    ldsm4(a[g][0], a[g][1], a[g][2], a[g][3],
                          Pw + (uint32_t)(g * 16 + (lane & 15)) * 128u + ca);
                uint32_t vb_kc = Vb + vrow + (uint32_t)(kc * 16) * 128u;
#pragma unroll
                for (int pd = 0; pd < 4; pd++) {
                    uint32_t cv = (uint32_t)(((2 * pd + ha) ^ keyx) << 4);
                    uint32_t bv0, bv1, bv2, bv3;
                    ldsm4t(bv0, bv1, bv2, bv3, vb_kc + cv);
                    mma16(oacc[0][2 * pd],     a[0][0], a[0][1], a[0][2], a[0][3], bv0, bv1);
                    mma16(oacc[1][2 * pd],     a[1][0], a[1][1], a[1][2], a[1][3], bv0, bv1);
                    mma16(oacc[0][2 * pd + 1], a[0][0], a[0][1], a[0][2], a[0][3], bv2, bv3);
                    mma16(oacc[1][2 * pd + 1], a[1][0], a[1][1], a[1][2], a[1][3], bv2, bv3);
                }
            }
            __syncwarp();
        }
    }

    // normalize + store fp16 to g_atth [B,T,C]
    int bb = bh >> 4, hh = bh & (HH - 1);
#pragma unroll
    for (int g = 0; g < 2; g++) {
#pragma unroll
        for (int h = 0; h < 2; h++) {
            int row = qw0 + g * 16 + (lane >> 2) + h * 8;
            float inv = 1.f / l_i[g][h];
#pragma unroll
            for (int nt = 0; nt < 8; nt++) {
                int col = hh * DD + nt * 8 + 2 * (lane & 3);
                __half2 r = __floats2half2_rn(oacc[g][nt][h * 2 + 0] * inv,
                                              oacc[g][nt][h * 2 + 1] * inv);
                *(__half2*)(g_atth + ((size_t)bb * TT + row) * CC + col) = r;
            }
        }
    }
}

// ===========================================================================
// Launch
// ===========================================================================
extern "C" void kernel_launch(void* const* d_in, const int* in_sizes, int n_in,
                              void* d_out, int out_size)
{
    (void)in_sizes; (void)n_in; (void)out_size;
    const float* x      = (const float*)d_in[0];
    const float* qkv_w  = (const float*)d_in[1];
    const float* qkv_b  = (const float*)d_in[2];
    const float* proj_w = (const float*)d_in[3];
    const float* proj_b = (const float*)d_in[4];
    float* out = (float*)d_out;

    cudaFuncSetAttribute(gemm_h,
                         cudaFuncAttributeMaxDynamicSharedMemorySize, SMEM_GEMM);
    cudaFuncSetAttribute(attn_h,
                         cudaFuncAttributeMaxDynamicSharedMemorySize, SMEM_ATTN);

    // Device addresses of __device__ symbols (query, not allocation).
    __half *xh, *wqh, *wph, *atth;
    cudaGetSymbolAddress((void**)&xh,   g_xh);
    cudaGetSymbolAddress((void**)&wqh,  g_wqh);
    cudaGetSymbolAddress((void**)&wph,  g_wph);
    cudaGetSymbolAddress((void**)&atth, g_atth);

    // 0) convert operands to fp16 (single launch)
    cvt_all<<<2048, 256>>>((const float4*)x, (const float4*)qkv_w,
                           (const float4*)proj_w);

    // 1) QKV projection + bias -> scatter fp16 [3][B,H,T,D]
    gemm_h<<<dim3(3 * CC / GBN, BB * TT / GBM), 256, SMEM_GEMM>>>(
        xh, wqh, qkv_b, nullptr, BB * TT, 3 * CC, CC, 1);

    // 2) Causal flash attention -> g_atth [B,T,C]
    attn_h<<<dim3(TT / 256, BB * HH), ATPB, SMEM_ATTN>>>();

    // 3) Output projection + bias -> d_out (fp32)
    gemm_h<<<dim3(CC / GBN, BB * TT / GBM), 256, SMEM_GEMM>>>(
        atth, wph, proj_b, out, BB * TT, CC, CC, 2);
}

// round 16
// speedup vs baseline: 1.8667x; 1.0447x over previous
#include <cuda_runtime.h>
#include <cuda_fp16.h>
#include <stdint.h>

// Problem constants
#define BB   4
#define TT   2048
#define CC   1024
#define HH   16
#define DD   64
#define BHTD (BB * HH * TT * DD)

// Scratch (device globals)
__device__ __half g_qkvh[3ull * BHTD];           // [3][B,H,T,D] fp16
__device__ __half g_atth[(size_t)BB * TT * CC];  // [B,T,C] fp16
__device__ __half g_xh[(size_t)BB * TT * CC];    // fp16(x)
__device__ __half g_wqh[3 * CC * CC];            // fp16(qkv_w)
__device__ __half g_wph[CC * CC];                // fp16(proj_w)

// ---------------------------------------------------------------------------
// helpers
// ---------------------------------------------------------------------------
__device__ __forceinline__ float ex2(float x) {
    float r;
    asm("ex2.approx.f32 %0, %1;" : "=f"(r) : "f"(x));
    return r;
}

__device__ __forceinline__ void mma16(float* c,
    uint32_t a0, uint32_t a1, uint32_t a2, uint32_t a3,
    uint32_t b0, uint32_t b1)
{
    asm volatile(
        "mma.sync.aligned.m16n8k16.row.col.f32.f16.f16.f32 "
        "{%0,%1,%2,%3},{%4,%5,%6,%7},{%8,%9},{%0,%1,%2,%3};"
        : "+f"(c[0]), "+f"(c[1]), "+f"(c[2]), "+f"(c[3])
        : "r"(a0), "r"(a1), "r"(a2), "r"(a3), "r"(b0), "r"(b1));
}

__device__ __forceinline__ void ldsm4(uint32_t& r0, uint32_t& r1,
                                      uint32_t& r2, uint32_t& r3, uint32_t addr)
{
    asm volatile("ldmatrix.sync.aligned.m8n8.x4.shared.b16 {%0,%1,%2,%3}, [%4];"
                 : "=r"(r0), "=r"(r1), "=r"(r2), "=r"(r3) : "r"(addr));
}
__device__ __forceinline__ void ldsm4t(uint32_t& r0, uint32_t& r1,
                                       uint32_t& r2, uint32_t& r3, uint32_t addr)
{
    asm volatile("ldmatrix.sync.aligned.m8n8.x4.trans.shared.b16 {%0,%1,%2,%3}, [%4];"
                 : "=r"(r0), "=r"(r1), "=r"(r2), "=r"(r3) : "r"(addr));
}

__device__ __forceinline__ void cp16(uint32_t smem, const void* gmem) {
    asm volatile("cp.async.cg.shared.global [%0], [%1], 16;\n"
                 :: "r"(smem), "l"(gmem));
}
__device__ __forceinline__ void cp16ca(uint32_t smem, const void* gmem) {
    asm volatile("cp.async.ca.shared.global [%0], [%1], 16;\n"
                 :: "r"(smem), "l"(gmem));
}
__device__ __forceinline__ void cp_commit() {
    asm volatile("cp.async.commit_group;\n" ::: "memory");
}
template <int N>
__device__ __forceinline__ void cp_wait() {
    asm volatile("cp.async.wait_group %0;\n" :: "n"(N) : "memory");
}

// ---------------------------------------------------------------------------
// Convert all fp32 operands to fp16 (one launch). float4 -> 2x half2.
// ---------------------------------------------------------------------------
#define N4_X  (BB * TT * CC / 4)
#define N4_WQ (3 * CC * CC / 4)
#define N4_WP (CC * CC / 4)

__global__ __launch_bounds__(256) void cvt_all(
    const float4* __restrict__ x, const float4* __restrict__ wq,
    const float4* __restrict__ wp)
{
    int total = N4_X + N4_WQ + N4_WP;
    int i = blockIdx.x * blockDim.x + threadIdx.x;
    int stride = gridDim.x * blockDim.x;
    for (; i < total; i += stride) {
        const float4* in; __half* out; int j;
        if (i < N4_X)              { in = x;  out = g_xh;  j = i; }
        else if (i < N4_X + N4_WQ) { in = wq; out = g_wqh; j = i - N4_X; }
        else                       { in = wp; out = g_wph; j = i - N4_X - N4_WQ; }
        float4 v = in[j];
        __half2 h0 = __floats2half2_rn(v.x, v.y);
        __half2 h1 = __floats2half2_rn(v.z, v.w);
        *(uint2*)(out + (size_t)j * 4) =
            make_uint2(*(uint32_t*)&h0, *(uint32_t*)&h1);
    }
}

// ===========================================================================
// FP16 tensor-core GEMM (unchanged from R15): CTA 128x256x64, 8 warps 64x64,
// m16n8k16 HMMA, LDSM loads, 3-stage cp.async ring.
// ===========================================================================
#define GBM 128
#define GBN 256
#define GBK 64
#define A_HALVES (GBM * GBK)
#define B_HALVES (GBN * GBK)
#define STAGE_BYTES ((A_HALVES + B_HALVES) * 2)
#define NSTAGE 3
#define SMEM_GEMM (NSTAGE * STAGE_BYTES)

__global__ __launch_bounds__(256, 1) void gemm_h(
    const __half* __restrict__ A, const __half* __restrict__ Bt,
    const float* __restrict__ bias, float* __restrict__ Cout,
    int M, int N, int K, int mode)
{
    extern __shared__ char smc[];
    int tid = threadIdx.x, lane = tid & 31, w = tid >> 5;
    int wm0 = (w >> 2) * 64;
    int wn0 = (w & 3) * 64;
    int m0 = blockIdx.y * GBM, n0 = blockIdx.x * GBN;

    uint32_t smem_base = (uint32_t)__cvta_generic_to_shared(smc);

    float acc[4][8][4];
#pragma unroll
    for (int mt = 0; mt < 4; mt++)
#pragma unroll
        for (int nt = 0; nt < 8; nt++)
#pragma unroll
            for (int j = 0; j < 4; j++) acc[mt][nt][j] = 0.f;

    int keyx = lane & 7;
    uint32_t ha = lane >> 4;
    uint32_t hb = (lane >> 3) & 1;
    uint32_t aab[4], bab[4];
#pragma unroll
    for (int mt = 0; mt < 4; mt++)
        aab[mt] = (uint32_t)(wm0 + mt * 16 + (lane & 15)) * 128u;
#pragma unroll
    for (int p = 0; p < 4; p++)
        bab[p] = (uint32_t)(wn0 + p * 16 + (lane & 7) + ((lane >> 4) << 3)) * 128u;

    int nK = K / GBK;

    auto stage_tile = [&](int st, int kk) {
        uint32_t sA = smem_base + (uint32_t)st * STAGE_BYTES;
        uint32_t sB = sA + A_HALVES * 2;
#pragma unroll
        for (int i = 0; i < 4; i++) {
            int l = tid + i * 256;
            int row = l >> 3, q = l & 7;
            uint32_t soff = (uint32_t)row * 128u + (uint32_t)((q ^ (row & 7)) << 4);
            cp16(sA + soff, A + (size_t)(m0 + row) * K + kk + q * 8);
        }
#pragma unroll
        for (int i = 0; i < 8; i++) {
            int l = tid + i * 256;
            int row = l >> 3, q = l & 7;
            uint32_t soff = (uint32_t)row * 128u + (uint32_t)((q ^ (row & 7)) << 4);
            cp16(sB + soff, Bt + (size_t)(n0 + row) * K + kk + q * 8);
        }
        cp_commit();
    };

    stage_tile(0, 0);
    stage_tile(1, GBK);

    int rd_stage = 0, wr_stage = 2;
    for (int kt = 0; kt < nK; kt++) {
        if (kt + 1 < nK) cp_wait<1>(); else cp_wait<0>();
        __syncthreads();

        if (kt + 2 < nK) stage_tile(wr_stage, (kt + 2) * GBK);
        if (++wr_stage == NSTAGE) wr_stage = 0;

        uint32_t As_b = smem_base + (uint32_t)rd_stage * STAGE_BYTES;
        uint32_t Bs_b = As_b + A_HALVES * 2;
        if (++rd_stage == NSTAGE) rd_stage = 0;

#pragma unroll
        for (int kc = 0; kc < 4; kc++) {
            uint32_t ca = (uint32_t)(((2 * kc + ha) ^ keyx) << 4);
            uint32_t cb = (uint32_t)(((2 * kc + hb) ^ keyx) << 4);
            uint32_t a[4][4];
#pragma unroll
            for (int mt = 0; mt < 4; mt++)
                ldsm4(a[mt][0], a[mt][1], a[mt][2], a[mt][3], As_b + aab[mt] + ca);
#pragma unroll
            for (int p = 0; p < 4; p++) {
                uint32_t bv0, bv1, bv2, bv3;
                ldsm4(bv0, bv1, bv2, bv3, Bs_b + bab[p] + cb);
#pragma unroll
                for (int mt = 0; mt < 4; mt++) {
                    mma16(acc[mt][2 * p],     a[mt][0], a[mt][1], a[mt][2], a[mt][3], bv0, bv1);
                    mma16(acc[mt][2 * p + 1], a[mt][0], a[mt][1], a[mt][2], a[mt][3], bv2, bv3);
                }
            }
        }
    }

#pragma unroll
    for (int mt = 0; mt < 4; mt++) {
#pragma unroll
        for (int h = 0; h < 2; h++) {
            int m = m0 + wm0 + mt * 16 + (lane >> 2) + h * 8;
#pragma unroll
            for (int nt = 0; nt < 8; nt++) {
                int n = n0 + wn0 + nt * 8 + 2 * (lane & 3);
                float rx = acc[mt][nt][h * 2 + 0] + bias[n];
                float ry = acc[mt][nt][h * 2 + 1] + bias[n + 1];
                if (mode == 1) {
                    int which = n >> 10;
                    int hh = (n >> 6) & (HH - 1);
                    int d = n & (DD - 1);
                    int b = m >> 11;
                    int t = m & (TT - 1);
                    __half* p = g_qkvh + (size_t)which * BHTD
                              + ((((size_t)b * HH + hh) * TT + t) * DD + d);
                    *(__half2*)p = __floats2half2_rn(rx, ry);
                } else {
                    float2 r; r.x = rx; r.y = ry;
                    *(float2*)(Cout + (size_t)m * N + n) = r;
                }
            }
        }
    }
}

// ===========================================================================
// FP16 flash attention v2 (causal): q-block 128, 4 warps x 32 rows,
// 2 CTAs/SM. K frags ldmatrix; V frags ldmatrix.trans; P staged half2.
// ===========================================================================
#define ATPB 128
#define ROWB 128                         // 64 halves per row
#define KVTILE (64 * ROWB)               // 8KB
#define KVSTG  (2 * KVTILE)              // K+V = 16KB per stage
#define PSMB   (4 * 32 * ROWB)           // 16KB (per-warp P)
#define SMEM_ATTN (2 * KVSTG + PSMB)     // 48KB
#define QSCALE (0.125f * 1.44269504088896f)

__global__ __launch_bounds__(ATPB, 2) void attn_h()
{
    extern __shared__ char smc[];
    uint32_t smem_base = (uint32_t)__cvta_generic_to_shared(smc);
    uint32_t psm_base = smem_base + 2 * KVSTG;

    int qb = gridDim.x - 1 - blockIdx.x;     // big blocks first
    int bh = blockIdx.y;
    int q0 = qb * 128;
    int tid = threadIdx.x, lane = tid & 31, w = tid >> 5;
    int qw0 = q0 + w * 32;

    const __half* qp = g_qkvh + (size_t)bh * TT * DD;
    const __half* kp = qp + (size_t)BHTD;
    const __half* vp = qp + 2ull * BHTD;

    auto stage_kv = [&](int st, int k0) {
        uint32_t kb = smem_base + (uint32_t)st * KVSTG;
        uint32_t vb = kb + KVTILE;
#pragma unroll
        for (int it = 0; it < 4; it++) {
            int l = tid + it * ATPB;     // 0..511
            int row = l >> 3, q = l & 7;
            uint32_t soff = (uint32_t)row * 128u + (uint32_t)((q ^ (row & 7)) << 4);
            cp16ca(kb + soff, kp + (size_t)(k0 + row) * DD + q * 8);
            cp16ca(vb + soff, vp + (size_t)(k0 + row) * DD + q * 8);
        }
        cp_commit();
    };

    stage_kv(0, 0);

    // fragment address bases
    int keyx = lane & 7;
    uint32_t krow[4];
#pragma unroll
    for (int p = 0; p < 4; p++)
        krow[p] = (uint32_t)(p * 16 + (lane & 7) + ((lane >> 4) << 3)) * 128u;
    uint32_t vrow = (uint32_t)((lane & 7) + (((lane >> 3) & 1) << 3)) * 128u;
    uint32_t hb = (lane >> 3) & 1;
    uint32_t ha = lane >> 4;

    // Q -> registers as fp16 A-frags, scale folded
    uint32_t qa[2][4][4];
#pragma unroll
    for (int g = 0; g < 2; g++) {
        int r = qw0 + g * 16 + (lane >> 2);
#pragma unroll
        for (int kc = 0; kc < 4; kc++) {
            int kb = kc * 16 + 2 * (lane & 3);
#pragma unroll
            for (int s = 0; s < 4; s++) {
                int rr = r + ((s & 1) ? 8 : 0);
                int cc = kb + ((s & 2) ? 8 : 0);
                float f0 = __half2float(qp[(size_t)rr * DD + cc])     * QSCALE;
                float f1 = __half2float(qp[(size_t)rr * DD + cc + 1]) * QSCALE;
                __half2 hq = __floats2half2_rn(f0, f1);
                qa[g][kc][s] = *(uint32_t*)&hq;
            }
        }
    }

    float m_i[2][2], l_i[2][2];
    float oacc[2][8][4];
#pragma unroll
    for (int g = 0; g < 2; g++) {
        m_i[g][0] = m_i[g][1] = -1e30f;
        l_i[g][0] = l_i[g][1] = 0.f;
#pragma unroll
        for (int nt = 0; nt < 8; nt++)
#pragma unroll
            for (int j = 0; j < 4; j++) oacc[g][nt][j] = 0.f;
    }

    int jbmax = 2 * qb + 1;
    for (int jb = 0; jb <= jbmax; jb++) {
        int k0 = jb * 64;
        cp_wait<0>();
        __syncthreads();

        if (jb < jbmax) stage_kv((jb + 1) & 1, k0 + 64);

        uint32_t Kb = smem_base + (uint32_t)((jb & 1) * KVSTG);
        uint32_t Vb = Kb + KVTILE;

        if (k0 <= qw0 + 31) {
            // S = Q K^T
            float sacc[2][8][4];
#pragma unroll
            for (int g = 0; g < 2; g++)
#pragma unroll
                for (int nt = 0; nt < 8; nt++)
#pragma unroll
                    for (int j = 0; j < 4; j++) sacc[g][nt][j] = 0.f;
#pragma unroll
            for (int kc = 0; kc < 4; kc++) {
                uint32_t cb = (uint32_t)(((2 * kc + hb) ^ keyx) << 4);
#pragma unroll
                for (int p = 0; p < 4; p++) {
                    uint32_t b0, b1, b2, b3;
                    ldsm4(b0, b1, b2, b3, Kb + krow[p] + cb);
                    mma16(sacc[0][2 * p],     qa[0][kc][0], qa[0][kc][1], qa[0][kc][2], qa[0][kc][3], b0, b1);
                    mma16(sacc[1][2 * p],     qa[1][kc][0], qa[1][kc][1], qa[1][kc][2], qa[1][kc][3], b0, b1);
                    mma16(sacc[0][2 * p + 1], qa[0][kc][0], qa[0][kc][1], qa[0][kc][2], qa[0][kc][3], b2, b3);
                    mma16(sacc[1][2 * p + 1], qa[1][kc][0], qa[1][kc][1], qa[1][kc][2], qa[1][kc][3], b2, b3);
                }
            }

            if (k0 + 63 > qw0) {
#pragma unroll
                for (int g = 0; g < 2; g++) {
                    int r0 = qw0 + g * 16 + (lane >> 2);
#pragma unroll
                    for (int nt = 0; nt < 8; nt++) {
                        int col = k0 + nt * 8 + 2 * (lane & 3);
                        if (col     > r0)     sacc[g][nt][0] = -1e30f;
                        if (col + 1 > r0)     sacc[g][nt][1] = -1e30f;
                        if (col     > r0 + 8) sacc[g][nt][2] = -1e30f;
                        if (col + 1 > r0 + 8) sacc[g][nt][3] = -1e30f;
                    }
                }
            }

            // online softmax (exp2 domain)
#pragma unroll
            for (int g = 0; g < 2; g++) {
#pragma unroll
                for (int h = 0; h < 2; h++) {
                    float mx = -1e30f;
#pragma unroll
                    for (int nt = 0; nt < 8; nt++) {
                        mx = fmaxf(mx, sacc[g][nt][h * 2 + 0]);
                        mx = fmaxf(mx, sacc[g][nt][h * 2 + 1]);
                    }
                    mx = fmaxf(mx, __shfl_xor_sync(0xffffffffu, mx, 1));
                    mx = fmaxf(mx, __shfl_xor_sync(0xffffffffu, mx, 2));
                    float mnew = fmaxf(m_i[g][h], mx);
                    float alpha = ex2(m_i[g][h] - mnew);
                    float rs = 0.f;
#pragma unroll
                    for (int nt = 0; nt < 8; nt++) {
                        float p0 = ex2(sacc[g][nt][h * 2 + 0] - mnew);
                        float p1 = ex2(sacc[g][nt][h * 2 + 1] - mnew);
                        sacc[g][nt][h * 2 + 0] = p0;
                        sacc[g][nt][h * 2 + 1] = p1;
                        rs += p0 + p1;
                    }
                    rs += __shfl_xor_sync(0xffffffffu, rs, 1);
                    rs += __shfl_xor_sync(0xffffffffu, rs, 2);
                    l_i[g][h] = l_i[g][h] * alpha + rs;
                    m_i[g][h] = mnew;
#pragma unroll
                    for (int nt = 0; nt < 8; nt++) {
                        oacc[g][nt][h * 2 + 0] *= alpha;
                        oacc[g][nt][h * 2 + 1] *= alpha;
                    }
                }
            }

            // P -> per-warp smem as fp16
            uint32_t Pw = psm_base + (uint32_t)w * 32 * ROWB;
#pragma unroll
            for (int g = 0; g < 2; g++) {
                int r0 = g * 16 + (lane >> 2);
#pragma unroll
                for (int nt = 0; nt < 8; nt++) {
                    uint32_t coff = (uint32_t)(((nt ^ (r0 & 7)) << 4) + 4 * (lane & 3));
                    __half2 p0 = __floats2half2_rn(sacc[g][nt][0], sacc[g][nt][1]);
                    __half2 p1 = __floats2half2_rn(sacc[g][nt][2], sacc[g][nt][3]);
                    *(__half2*)(smc + (Pw - smem_base) + (uint32_t)r0 * 128u + coff) = p0;
                    *(__half2*)(smc + (Pw - smem_base) + (uint32_t)(r0 + 8) * 128u + coff) = p1;
                }
            }
            __syncwarp();

            // O += P V   (A: ldsm on P; B: ldsm.trans on V)
#pragma unroll
            for (int kc = 0; kc < 4; kc++) {
                uint32_t ca = (uint32_t)(((2 * kc + ha) ^ keyx) << 4);
                uint32_t a[2][4];
#pragma unroll
                for (int g = 0; g < 2; g++)
                    ldsm4(a[g][0], a[g][1], a[g][2], a[g][3],
                          Pw + (uint32_t)(g * 16 + (lane & 15)) * 128u + ca);
                uint32_t vb_kc = Vb + vrow + (uint32_t)(kc * 16) * 128u;
#pragma unroll
                for (int pd = 0; pd < 4; pd++) {
                    uint32_t cv = (uint32_t)(((2 * pd + ha) ^ keyx) << 4);
                    uint32_t bv0, bv1, bv2, bv3;
                    ldsm4t(bv0, bv1, bv2, bv3, vb_kc + cv);
                    mma16(oacc[0][2 * pd],     a[0][0], a[0][1], a[0][2], a[0][3], bv0, bv1);
                    mma16(oacc[1][2 * pd],     a[1][0], a[1][1], a[1][2], a[1][3], bv0, bv1);
                    mma16(oacc[0][2 * pd + 1], a[0][0], a[0][1], a[0][2], a[0][3], bv2, bv3);
                    mma16(oacc[1][2 * pd + 1], a[1][0], a[1][1], a[1][2], a[1][3], bv2, bv3);
                }
            }
            __syncwarp();
        }
    }

    // normalize + store fp16 to g_atth [B,T,C]
    int bb = bh >> 4, hh = bh & (HH - 1);
#pragma unroll
    for (int g = 0; g < 2; g++) {
#pragma unroll
        for (int h = 0; h < 2; h++) {
            int row = qw0 + g * 16 + (lane >> 2) + h * 8;
            float inv = 1.f / l_i[g][h];
#pragma unroll
            for (int nt = 0; nt < 8; nt++) {
                int col = hh * DD + nt * 8 + 2 * (lane & 3);
                __half2 r = __floats2half2_rn(oacc[g][nt][h * 2 + 0] * inv,
                                              oacc[g][nt][h * 2 + 1] * inv);
                *(__half2*)(g_atth + ((size_t)bb * TT + row) * CC + col) = r;
            }
        }
    }
}

// ===========================================================================
// Launch
// ===========================================================================
extern "C" void kernel_launch(void* const* d_in, const int* in_sizes, int n_in,
                              void* d_out, int out_size)
{
    (void)in_sizes; (void)n_in; (void)out_size;
    const float* x      = (const float*)d_in[0];
    const float* qkv_w  = (const float*)d_in[1];
    const float* qkv_b  = (const float*)d_in[2];
    const float* proj_w = (const float*)d_in[3];
    const float* proj_b = (const float*)d_in[4];
    float* out = (float*)d_out;

    cudaFuncSetAttribute(gemm_h,
                         cudaFuncAttributeMaxDynamicSharedMemorySize, SMEM_GEMM);
    cudaFuncSetAttribute(attn_h,
                         cudaFuncAttributeMaxDynamicSharedMemorySize, SMEM_ATTN);

    // Device addresses of __device__ symbols (query, not allocation).
    __half *xh, *wqh, *wph, *atth;
    cudaGetSymbolAddress((void**)&xh,   g_xh);
    cudaGetSymbolAddress((void**)&wqh,  g_wqh);
    cudaGetSymbolAddress((void**)&wph,  g_wph);
    cudaGetSymbolAddress((void**)&atth, g_atth);

    // 0) convert operands to fp16 (single launch)
    cvt_all<<<2048, 256>>>((const float4*)x, (const float4*)qkv_w,
                           (const float4*)proj_w);

    // 1) QKV projection + bias -> scatter fp16 [3][B,H,T,D]
    gemm_h<<<dim3(3 * CC / GBN, BB * TT / GBM), 256, SMEM_GEMM>>>(
        xh, wqh, qkv_b, nullptr, BB * TT, 3 * CC, CC, 1);

    // 2) Causal flash attention -> g_atth [B,T,C]
    attn_h<<<dim3(TT / 128, BB * HH), ATPB, SMEM_ATTN>>>();

    // 3) Output projection + bias -> d_out (fp32)
    gemm_h<<<dim3(CC / GBN, BB * TT / GBM), 256, SMEM_GEMM>>>(
        atth, wph, proj_b, out, BB * TT, CC, CC, 2);
}